// round 15
// baseline (speedup 1.0000x reference)
#include <cuda_runtime.h>
#include <cuda_fp16.h>

#define EMBED 1024
#define NHEADS 16
#define HDIM 64
#define SEQ 2048
#define NCLS 1000
#define GCHUNKS 16
#define MTOT 4096

#define BM 128
#define BN 128
#define BKE 64
#define NIT (EMBED / BKE)          // 16
#define PK 72                      // padded row (elems): 144B, ldmatrix conflict-free
#define TILEB (BM * PK * 2)        // 18432 B per tile
#define STAGEB (2 * TILEB)         // 36864 {A, B}
#define SMEM_BYTES (2 * STAGEB)    // 73728 -> 2 CTAs/SM

#define WSCALE 32.0f               // W_in pre-scale
#define B2SCALE 16.0f              // B2 pre-scale

// ---------- scratch ----------
__device__ float g_G[32 * HDIM * HDIM];
__device__ float g_Gpart[GCHUNKS][32][HDIM * HDIM];
__device__ __half g_xh[MTOT * EMBED];
__device__ __half g_wh[EMBED * EMBED];
__device__ __half g_phh[MTOT * EMBED];        // fp16 P (GEMM2 A + gram source)
__device__ __half g_b2h[2 * 1024 * EMBED];

// ---------- helpers ----------
__device__ __forceinline__ unsigned smem_u32(const void* p) {
    unsigned a;
    asm("{ .reg .u64 t; cvta.to.shared.u64 t, %1; cvt.u32.u64 %0, t; }" : "=r"(a) : "l"(p));
    return a;
}
__device__ __forceinline__ void cpa16(unsigned s, const void* g) {
    asm volatile("cp.async.cg.shared.global [%0], [%1], 16;" :: "r"(s), "l"(g) : "memory");
}
#define CP_COMMIT() asm volatile("cp.async.commit_group;" ::: "memory")
#define CP_WAIT(n)  asm volatile("cp.async.wait_group %0;" :: "n"(n) : "memory")

#define LDSM4(r0, r1, r2, r3, a) \
    asm volatile("ldmatrix.sync.aligned.m8n8.x4.shared.b16 {%0,%1,%2,%3}, [%4];" \
        : "=r"(r0), "=r"(r1), "=r"(r2), "=r"(r3) : "r"(a))

#define LDSM4T(r0, r1, r2, r3, a) \
    asm volatile("ldmatrix.sync.aligned.m8n8.x4.trans.shared.b16 {%0,%1,%2,%3}, [%4];" \
        : "=r"(r0), "=r"(r1), "=r"(r2), "=r"(r3) : "r"(a))

#define MMAH(c, a, b0v, b1v) \
    asm volatile("mma.sync.aligned.m16n8k16.row.col.f32.f16.f16.f32 " \
        "{%0,%1,%2,%3},{%4,%5,%6,%7},{%8,%9},{%0,%1,%2,%3};" \
        : "+f"((c)[0]), "+f"((c)[1]), "+f"((c)[2]), "+f"((c)[3]) \
        : "r"((a)[0]), "r"((a)[1]), "r"((a)[2]), "r"((a)[3]), "r"(b0v), "r"(b1v))

__device__ __forceinline__ unsigned h2bits(__half2 h) {
    return *reinterpret_cast<unsigned*>(&h);
}

// ---------- cvt: x (scale 1) and W_in (scale WSCALE) in one launch ----------
__global__ void cvt_both(const float4* __restrict__ X, uint2* __restrict__ XH, int nx4,
                         const float4* __restrict__ W, uint2* __restrict__ WH, int nw4)
{
    int i = blockIdx.x * blockDim.x + threadIdx.x;
    if (i < nx4) {
        float4 x = X[i];
        XH[i] = make_uint2(h2bits(__floats2half2_rn(x.x, x.y)),
                           h2bits(__floats2half2_rn(x.z, x.w)));
    }
    int j = i - nx4;
    if (j >= 0 && j < nw4) {
        float4 w = W[j];
        WH[j] = make_uint2(h2bits(__floats2half2_rn(w.x * WSCALE, w.y * WSCALE)),
                           h2bits(__floats2half2_rn(w.z * WSCALE, w.w * WSCALE)));
    }
}

// ---------- fp16 single-term GEMM: C = (A @ B^T)*postScale + bias ----------
__device__ __forceinline__ void load_stage(
    unsigned sbuf, int tid, int k0,
    const __half* A, const __half* B, int m0, int n0)
{
    int row = tid >> 1;
    int hf = tid & 1;                  // 32-elem half of 64
    unsigned soff = (unsigned)(row * PK + hf * 32) * 2;
    size_t ga = (size_t)(m0 + row) * EMBED + k0 + hf * 32;
    size_t gb = (size_t)(n0 + row) * EMBED + k0 + hf * 32;
#pragma unroll
    for (int g = 0; g < 4; g++) {
        cpa16(sbuf + soff + g * 16,         A + ga + g * 8);
        cpa16(sbuf + TILEB + soff + g * 16, B + gb + g * 8);
    }
}

__global__ __launch_bounds__(256, 2) void gemm_fp16(
    const __half* __restrict__ A, const __half* __restrict__ BBase,
    const float* __restrict__ bias, float postScale, float* __restrict__ C,
    __half* __restrict__ Ph, int N, long bStride)
{
    extern __shared__ char smc[];
    int tid = threadIdx.x;
    int m0 = blockIdx.y * BM;
    int n0 = blockIdx.x * BN;
    unsigned sbase = smem_u32(smc);

    const __half* B = BBase + (size_t)(m0 >> 11) * bStride;

    int wid = tid >> 5, lane = tid & 31;
    int wm = (wid & 1) * 64;
    int wn = (wid >> 1) * 32;

    float acc[4][4][4];
#pragma unroll
    for (int i = 0; i < 4; i++)
#pragma unroll
        for (int j = 0; j < 4; j++)
#pragma unroll
            for (int v = 0; v < 4; v++) acc[i][j][v] = 0.f;

    load_stage(sbase, tid, 0, A, B, m0, n0);
    CP_COMMIT();

    unsigned a_lo = (unsigned)((wm + (lane & 15)) * PK + ((lane >> 4) << 3)) * 2;
    unsigned b_lo = (unsigned)((wn + (lane & 15)) * PK + ((lane >> 4) << 3)) * 2;

    for (int it = 0; it < NIT; it++) {
        CP_WAIT(0);
        __syncthreads();
        if (it + 1 < NIT) {
            load_stage(sbase + (unsigned)((it + 1) & 1) * STAGEB, tid,
                       (it + 1) * BKE, A, B, m0, n0);
            CP_COMMIT();
        }

        unsigned sbuf = sbase + (unsigned)(it & 1) * STAGEB;
#pragma unroll
        for (int kk = 0; kk < 4; kk++) {
            unsigned ah[4][4], bb[2][4];
            unsigned ao = sbuf + a_lo + (unsigned)kk * 32;
            unsigned bo = sbuf + b_lo + (unsigned)kk * 32;

#pragma unroll
            for (int i = 0; i < 4; i++)
                LDSM4(ah[i][0], ah[i][1], ah[i][2], ah[i][3],
                      ao + (unsigned)i * (16 * PK * 2));
#pragma unroll
            for (int L = 0; L < 2; L++)
                LDSM4(bb[L][0], bb[L][1], bb[L][2], bb[L][3],
                      bo + TILEB + (unsigned)L * (16 * PK * 2));
#pragma unroll
            for (int i = 0; i < 4; i++)
#pragma unroll
                for (int j = 0; j < 4; j++) {
                    int L = j >> 1, s = j & 1;
                    MMAH(acc[i][j], ah[i], bb[L][s], bb[L][s + 2]);
                }
        }
    }

    // epilogue
    int r = lane >> 2, c2 = (lane & 3) * 2;
#pragma unroll
    for (int i = 0; i < 4; i++) {
        int m = m0 + wm + i * 16 + r;
#pragma unroll
        for (int j = 0; j < 4; j++) {
            int n = n0 + wn + j * 8 + c2;
            float bv0 = (n < N) ? bias[n] : 0.f;
            float bv1 = (n + 1 < N) ? bias[n + 1] : 0.f;
            float v00 = acc[i][j][0] * postScale + bv0;
            float v01 = acc[i][j][1] * postScale + bv1;
            float v10 = acc[i][j][2] * postScale + bv0;
            float v11 = acc[i][j][3] * postScale + bv1;
            if (C) {
                float* C0 = C + (size_t)m * N;
                float* C1 = C0 + (size_t)8 * N;
                if (n < N)     { C0[n] = v00; C1[n] = v10; }
                if (n + 1 < N) { C0[n + 1] = v01; C1[n + 1] = v11; }
            }
            if (Ph) {
                *(unsigned*)(Ph + (size_t)m * EMBED + n) =
                    h2bits(__floats2half2_rn(v00, v01));
                *(unsigned*)(Ph + (size_t)(m + 8) * EMBED + n) =
                    h2bits(__floats2half2_rn(v10, v11));
            }
        }
    }
}

// ---------- fp16 Gram: Gpart[chunk][bh] = P_h^T P_h over 128 s-rows ----------
#define GPD 72

__global__ __launch_bounds__(256, 4) void head_gram_fp16(
    const __half* __restrict__ ph, float* __restrict__ Gpart)
{
    __shared__ __half sh[128][GPD];

    int bh = blockIdx.x;
    int chunk = blockIdx.y;
    int b = bh >> 4;
    int h = bh & 15;
    int tid = threadIdx.x;
    int wid = tid >> 5, lane = tid & 31;
    int wm = (wid & 1) * 32;
    int wn = (wid >> 1) * 16;

    unsigned shB = smem_u32(&sh[0][0]);

    int g = lane >> 3, l = lane & 7;
    unsigned aRowOff = (unsigned)(((g & 2) ? 8 : 0) + l) * (GPD * 2);
    unsigned aColOff = (unsigned)(wm + ((g & 1) ? 8 : 0)) * 2;
    unsigned bRowOff = (unsigned)(((g & 1) ? 8 : 0) + l) * (GPD * 2);
    unsigned bColOff = (unsigned)(wn + ((g >= 2) ? 8 : 0)) * 2;

    float acc[2][2][4];
#pragma unroll
    for (int i = 0; i < 2; i++)
#pragma unroll
        for (int j = 0; j < 2; j++)
#pragma unroll
            for (int v = 0; v < 4; v++) acc[i][j][v] = 0.f;

    int row = tid >> 1;
    int q = tid & 1;
    unsigned soff = (unsigned)(row * GPD + q * 32) * 2;

    size_t gbase = (size_t)(b * SEQ + chunk * 128 + row) * EMBED + h * HDIM + q * 32;
#pragma unroll
    for (int t = 0; t < 4; t++)
        cpa16(shB + soff + t * 16, ph + gbase + t * 8);
    CP_COMMIT();
    CP_WAIT(0);
    __syncthreads();

#pragma unroll
    for (int k0 = 0; k0 < 128; k0 += 16) {
        unsigned kb = (unsigned)k0 * (GPD * 2);
        unsigned A2[2][4], B4[4];
#pragma unroll
        for (int i = 0; i < 2; i++)
            LDSM4T(A2[i][0], A2[i][1], A2[i][2], A2[i][3],
                   shB + kb + aRowOff + aColOff + (unsigned)i * 32);
        LDSM4T(B4[0], B4[1], B4[2], B4[3], shB + kb + bRowOff + bColOff);

#pragma unroll
        for (int i = 0; i < 2; i++)
#pragma unroll
            for (int j = 0; j < 2; j++)
                MMAH(acc[i][j], A2[i], B4[j * 2], B4[j * 2 + 1]);
    }

    float* Gp = Gpart + ((size_t)chunk * 32 + bh) * (HDIM * HDIM);
    int r = lane >> 2, c2 = (lane & 3) * 2;
#pragma unroll
    for (int i = 0; i < 2; i++) {
        int d1a = wm + i * 16 + r;
#pragma unroll
        for (int j = 0; j < 2; j++) {
            int d2 = wn + j * 8 + c2;
            Gp[d1a * HDIM + d2]           = acc[i][j][0];
            Gp[d1a * HDIM + d2 + 1]       = acc[i][j][1];
            Gp[(d1a + 8) * HDIM + d2]     = acc[i][j][2];
            Gp[(d1a + 8) * HDIM + d2 + 1] = acc[i][j][3];
        }
    }
}

__global__ void gram_reduce(const float* __restrict__ Gpart,
                            float* __restrict__ G, float scale)
{
    int idx = blockIdx.x * blockDim.x + threadIdx.x;
    if (idx >= 32 * HDIM * HDIM) return;
    float s = 0.f;
#pragma unroll
    for (int c = 0; c < GCHUNKS; c++)
        s += Gpart[(size_t)c * 32 * HDIM * HDIM + idx];
    G[idx] = s * scale;
}

// ---------- fused B2 build: fp16, pre-scaled ----------
__global__ __launch_bounds__(256) void w2_build(
    const float* __restrict__ Wo, const float* __restrict__ G,
    __half* __restrict__ B2h)
{
    int c0 = blockIdx.x * 64;
    int h  = blockIdx.y;
    int b  = blockIdx.z;
    const float* Gh = G + (size_t)(b * NHEADS + h) * HDIM * HDIM;

    __shared__ float Gs[64][65];
    __shared__ float Ws[64][65];
    int tid = threadIdx.x;

#pragma unroll
    for (int v = 0; v < 4; v++) {
        int idx = tid + v * 256;
        int rr = idx >> 4;
        int c = (idx & 15) << 2;
        float4 g4 = *(const float4*)(Gh + rr * HDIM + c);
        Gs[rr][c + 0] = g4.x; Gs[rr][c + 1] = g4.y;
        Gs[rr][c + 2] = g4.z; Gs[rr][c + 3] = g4.w;
        float4 w4 = make_float4(0.f, 0.f, 0.f, 0.f);
        if (c0 + rr < NCLS)
            w4 = *(const float4*)(Wo + (size_t)(c0 + rr) * EMBED + h * HDIM + c);
        Ws[rr][c + 0] = w4.x; Ws[rr][c + 1] = w4.y;
        Ws[rr][c + 2] = w4.z; Ws[rr][c + 3] = w4.w;
    }
    __syncthreads();

    int j  = tid & 63;
    int i0 = (tid >> 6) << 4;
    float acc[16];
#pragma unroll
    for (int ii = 0; ii < 16; ii++) acc[ii] = 0.f;

#pragma unroll 4
    for (int k = 0; k < 64; k++) {
        float g = Gs[k][j];
#pragma unroll
        for (int ii = 0; ii < 16; ii++)
            acc[ii] += Ws[i0 + ii][k] * g;
    }

#pragma unroll
    for (int ii = 0; ii < 16; ii++) {
        size_t o = (size_t)b * 1024 * EMBED + (size_t)(c0 + i0 + ii) * EMBED + h * HDIM + j;
        B2h[o] = __float2half_rn(acc[ii] * B2SCALE);
    }
}

// ---------- launch ----------
extern "C" void kernel_launch(void* const* d_in, const int* in_sizes, int n_in,
                              void* d_out, int out_size)
{
    const float* x     = (const float*)d_in[0];
    const float* W_in  = (const float*)d_in[1];
    const float* b_in  = (const float*)d_in[2];
    const float* W_out = (const float*)d_in[3];
    const float* b_out = (const float*)d_in[4];
    float* out = (float*)d_out;

    int M = in_sizes[0] / EMBED;   // 4096

    float *G, *Gp;
    cudaGetSymbolAddress((void**)&G, g_G);
    cudaGetSymbolAddress((void**)&Gp, g_Gpart);
    __half *xh, *wh, *phh, *b2h;
    cudaGetSymbolAddress((void**)&xh, g_xh);
    cudaGetSymbolAddress((void**)&wh, g_wh);
    cudaGetSymbolAddress((void**)&phh, g_phh);
    cudaGetSymbolAddress((void**)&b2h, g_b2h);

    cudaFuncSetAttribute(gemm_fp16, cudaFuncAttributeMaxDynamicSharedMemorySize, SMEM_BYTES);

    dim3 blk(256);

    // quantize x and W_in in one launch
    int nx4 = M * EMBED / 4, nw4 = EMBED * EMBED / 4;
    cvt_both<<<(nx4 + nw4 + 255) / 256, blk>>>((const float4*)x, (uint2*)xh, nx4,
                                               (const float4*)W_in, (uint2*)wh, nw4);

    // 1) P = X @ W_in^T + b_in  (fp16 -> phh)
    gemm_fp16<<<dim3(EMBED / BN, M / BM), blk, SMEM_BYTES>>>(
        xh, wh, b_in, 1.0f / WSCALE, nullptr, phh, EMBED, 0);

    // 2) G = (1/32) * phh_h^T phh_h
    head_gram_fp16<<<dim3(32, GCHUNKS), blk>>>(phh, Gp);
    gram_reduce<<<(32 * HDIM * HDIM + 255) / 256, blk>>>(Gp, G, 1.0f / 32.0f);

    // 3) B2[b] = blockdiag(G) @ W_out^T  (fp16, x16)
    w2_build<<<dim3(1024 / 64, NHEADS, M / SEQ), blk>>>(W_out, G, b2h);

    // 4) out = P @ B2[b]^T + b_out  (fp16)
    gemm_fp16<<<dim3(1024 / BN, M / BM), blk, SMEM_BYTES>>>(
        phh, b2h, b_out, 1.0f / B2SCALE, out, nullptr, NCLS, (long)1024 * EMBED);
}

// round 16
// speedup vs baseline: 1.1074x; 1.1074x over previous
#include <cuda_runtime.h>
#include <cuda_fp16.h>

#define EMBED 1024
#define NHEADS 16
#define HDIM 64
#define SEQ 2048
#define NCLS 1000
#define GCHUNKS 16
#define MTOT 4096

#define BM 128
#define BN 128
#define BKE 32
#define NIT (EMBED / BKE)          // 32
#define PK 40                      // padded row (elems): 80B, ldmatrix conflict-free
#define TILEB (BM * PK * 2)        // 10240 B per tile
#define STAGEB (2 * TILEB)         // 20480 {A, B}
#define NSTAGE 3
#define SMEM_BYTES (NSTAGE * STAGEB)   // 61440 -> 2 CTAs/SM

#define WSCALE 32.0f               // W_in pre-scale
#define B2SCALE 16.0f              // B2 pre-scale

// ---------- scratch ----------
__device__ float g_G[32 * HDIM * HDIM];
__device__ float g_Gpart[GCHUNKS][32][HDIM * HDIM];
__device__ __half g_xh[MTOT * EMBED];
__device__ __half g_wh[EMBED * EMBED];
__device__ __half g_phh[MTOT * EMBED];        // fp16 P (GEMM2 A + gram source)
__device__ __half g_b2h[2 * 1024 * EMBED];

// ---------- helpers ----------
__device__ __forceinline__ unsigned smem_u32(const void* p) {
    unsigned a;
    asm("{ .reg .u64 t; cvta.to.shared.u64 t, %1; cvt.u32.u64 %0, t; }" : "=r"(a) : "l"(p));
    return a;
}
__device__ __forceinline__ void cpa16(unsigned s, const void* g) {
    asm volatile("cp.async.cg.shared.global [%0], [%1], 16;" :: "r"(s), "l"(g) : "memory");
}
#define CP_COMMIT() asm volatile("cp.async.commit_group;" ::: "memory")
#define CP_WAIT(n)  asm volatile("cp.async.wait_group %0;" :: "n"(n) : "memory")

#define LDSM4(r0, r1, r2, r3, a) \
    asm volatile("ldmatrix.sync.aligned.m8n8.x4.shared.b16 {%0,%1,%2,%3}, [%4];" \
        : "=r"(r0), "=r"(r1), "=r"(r2), "=r"(r3) : "r"(a))

#define LDSM4T(r0, r1, r2, r3, a) \
    asm volatile("ldmatrix.sync.aligned.m8n8.x4.trans.shared.b16 {%0,%1,%2,%3}, [%4];" \
        : "=r"(r0), "=r"(r1), "=r"(r2), "=r"(r3) : "r"(a))

#define MMAH(c, a, b0v, b1v) \
    asm volatile("mma.sync.aligned.m16n8k16.row.col.f32.f16.f16.f32 " \
        "{%0,%1,%2,%3},{%4,%5,%6,%7},{%8,%9},{%0,%1,%2,%3};" \
        : "+f"((c)[0]), "+f"((c)[1]), "+f"((c)[2]), "+f"((c)[3]) \
        : "r"((a)[0]), "r"((a)[1]), "r"((a)[2]), "r"((a)[3]), "r"(b0v), "r"(b1v))

__device__ __forceinline__ unsigned h2bits(__half2 h) {
    return *reinterpret_cast<unsigned*>(&h);
}

// ---------- cvt: x (scale 1) and W_in (scale WSCALE) in one launch ----------
__global__ void cvt_both(const float4* __restrict__ X, uint2* __restrict__ XH, int nx4,
                         const float4* __restrict__ W, uint2* __restrict__ WH, int nw4)
{
    int i = blockIdx.x * blockDim.x + threadIdx.x;
    if (i < nx4) {
        float4 x = X[i];
        XH[i] = make_uint2(h2bits(__floats2half2_rn(x.x, x.y)),
                           h2bits(__floats2half2_rn(x.z, x.w)));
    }
    int j = i - nx4;
    if (j >= 0 && j < nw4) {
        float4 w = W[j];
        WH[j] = make_uint2(h2bits(__floats2half2_rn(w.x * WSCALE, w.y * WSCALE)),
                           h2bits(__floats2half2_rn(w.z * WSCALE, w.w * WSCALE)));
    }
}

// ---------- fp16 single-term GEMM, 3-stage cp.async ring ----------
__device__ __forceinline__ void load_stage(
    unsigned sbuf, int tid, int k0,
    const __half* A, const __half* B, int m0, int n0)
{
    int row = tid >> 1;
    int hf = tid & 1;
    unsigned soff = (unsigned)(row * PK + hf * 16) * 2;
    size_t ga = (size_t)(m0 + row) * EMBED + k0 + hf * 16;
    size_t gb = (size_t)(n0 + row) * EMBED + k0 + hf * 16;
    cpa16(sbuf + soff,              A + ga);
    cpa16(sbuf + soff + 16,         A + ga + 8);
    cpa16(sbuf + TILEB + soff,      B + gb);
    cpa16(sbuf + TILEB + soff + 16, B + gb + 8);
}

__global__ __launch_bounds__(256, 2) void gemm_fp16(
    const __half* __restrict__ A, const __half* __restrict__ BBase,
    const float* __restrict__ bias, float postScale, float* __restrict__ C,
    __half* __restrict__ Ph, int N, long bStride)
{
    extern __shared__ char smc[];
    int tid = threadIdx.x;
    int m0 = blockIdx.y * BM;
    int n0 = blockIdx.x * BN;
    unsigned sbase = smem_u32(smc);

    const __half* B = BBase + (size_t)(m0 >> 11) * bStride;

    int wid = tid >> 5, lane = tid & 31;
    int wm = (wid & 1) * 64;
    int wn = (wid >> 1) * 32;

    float acc[4][4][4];
#pragma unroll
    for (int i = 0; i < 4; i++)
#pragma unroll
        for (int j = 0; j < 4; j++)
#pragma unroll
            for (int v = 0; v < 4; v++) acc[i][j][v] = 0.f;

    // prologue: stages 0, 1
    load_stage(sbase, tid, 0, A, B, m0, n0);
    CP_COMMIT();
    load_stage(sbase + STAGEB, tid, BKE, A, B, m0, n0);
    CP_COMMIT();

    unsigned a_lo = (unsigned)((wm + (lane & 15)) * PK + ((lane >> 4) << 3)) * 2;
    unsigned b_lo = (unsigned)((wn + (lane & 15)) * PK + ((lane >> 4) << 3)) * 2;

    for (int it = 0; it < NIT; it++) {
        CP_WAIT(1);            // load(it) complete; load(it+1) may still fly
        __syncthreads();       // all warps done reading slot (it-1)%3
        if (it + 2 < NIT) {
            load_stage(sbase + (unsigned)((it + 2) % NSTAGE) * STAGEB, tid,
                       (it + 2) * BKE, A, B, m0, n0);
        }
        CP_COMMIT();

        unsigned sbuf = sbase + (unsigned)(it % NSTAGE) * STAGEB;
#pragma unroll
        for (int kk = 0; kk < 2; kk++) {
            unsigned ah[4][4], bb[2][4];
            unsigned ao = sbuf + a_lo + (unsigned)kk * 32;
            unsigned bo = sbuf + b_lo + (unsigned)kk * 32;

#pragma unroll
            for (int i = 0; i < 4; i++)
                LDSM4(ah[i][0], ah[i][1], ah[i][2], ah[i][3],
                      ao + (unsigned)i * (16 * PK * 2));
#pragma unroll
            for (int L = 0; L < 2; L++)
                LDSM4(bb[L][0], bb[L][1], bb[L][2], bb[L][3],
                      bo + TILEB + (unsigned)L * (16 * PK * 2));
#pragma unroll
            for (int i = 0; i < 4; i++)
#pragma unroll
                for (int j = 0; j < 4; j++) {
                    int L = j >> 1, s = j & 1;
                    MMAH(acc[i][j], ah[i], bb[L][s], bb[L][s + 2]);
                }
        }
    }

    // epilogue
    int r = lane >> 2, c2 = (lane & 3) * 2;
#pragma unroll
    for (int i = 0; i < 4; i++) {
        int m = m0 + wm + i * 16 + r;
#pragma unroll
        for (int j = 0; j < 4; j++) {
            int n = n0 + wn + j * 8 + c2;
            float bv0 = (n < N) ? bias[n] : 0.f;
            float bv1 = (n + 1 < N) ? bias[n + 1] : 0.f;
            float v00 = acc[i][j][0] * postScale + bv0;
            float v01 = acc[i][j][1] * postScale + bv1;
            float v10 = acc[i][j][2] * postScale + bv0;
            float v11 = acc[i][j][3] * postScale + bv1;
            if (C) {
                float* C0 = C + (size_t)m * N;
                float* C1 = C0 + (size_t)8 * N;
                if (n < N)     { C0[n] = v00; C1[n] = v10; }
                if (n + 1 < N) { C0[n + 1] = v01; C1[n + 1] = v11; }
            }
            if (Ph) {
                *(unsigned*)(Ph + (size_t)m * EMBED + n) =
                    h2bits(__floats2half2_rn(v00, v01));
                *(unsigned*)(Ph + (size_t)(m + 8) * EMBED + n) =
                    h2bits(__floats2half2_rn(v10, v11));
            }
        }
    }
}

// ---------- fp16 Gram: Gpart[chunk][bh] = P_h^T P_h over 128 s-rows ----------
#define GPD 72

__global__ __launch_bounds__(256, 4) void head_gram_fp16(
    const __half* __restrict__ ph, float* __restrict__ Gpart)
{
    __shared__ __half sh[128][GPD];

    int bh = blockIdx.x;
    int chunk = blockIdx.y;
    int b = bh >> 4;
    int h = bh & 15;
    int tid = threadIdx.x;
    int wid = tid >> 5, lane = tid & 31;
    int wm = (wid & 1) * 32;
    int wn = (wid >> 1) * 16;

    unsigned shB = smem_u32(&sh[0][0]);

    int g = lane >> 3, l = lane & 7;
    unsigned aRowOff = (unsigned)(((g & 2) ? 8 : 0) + l) * (GPD * 2);
    unsigned aColOff = (unsigned)(wm + ((g & 1) ? 8 : 0)) * 2;
    unsigned bRowOff = (unsigned)(((g & 1) ? 8 : 0) + l) * (GPD * 2);
    unsigned bColOff = (unsigned)(wn + ((g >= 2) ? 8 : 0)) * 2;

    float acc[2][2][4];
#pragma unroll
    for (int i = 0; i < 2; i++)
#pragma unroll
        for (int j = 0; j < 2; j++)
#pragma unroll
            for (int v = 0; v < 4; v++) acc[i][j][v] = 0.f;

    int row = tid >> 1;
    int q = tid & 1;
    unsigned soff = (unsigned)(row * GPD + q * 32) * 2;

    size_t gbase = (size_t)(b * SEQ + chunk * 128 + row) * EMBED + h * HDIM + q * 32;
#pragma unroll
    for (int t = 0; t < 4; t++)
        cpa16(shB + soff + t * 16, ph + gbase + t * 8);
    CP_COMMIT();
    CP_WAIT(0);
    __syncthreads();

#pragma unroll
    for (int k0 = 0; k0 < 128; k0 += 16) {
        unsigned kb = (unsigned)k0 * (GPD * 2);
        unsigned A2[2][4], B4[4];
#pragma unroll
        for (int i = 0; i < 2; i++)
            LDSM4T(A2[i][0], A2[i][1], A2[i][2], A2[i][3],
                   shB + kb + aRowOff + aColOff + (unsigned)i * 32);
        LDSM4T(B4[0], B4[1], B4[2], B4[3], shB + kb + bRowOff + bColOff);

#pragma unroll
        for (int i = 0; i < 2; i++)
#pragma unroll
            for (int j = 0; j < 2; j++)
                MMAH(acc[i][j], A2[i], B4[j * 2], B4[j * 2 + 1]);
    }

    float* Gp = Gpart + ((size_t)chunk * 32 + bh) * (HDIM * HDIM);
    int r = lane >> 2, c2 = (lane & 3) * 2;
#pragma unroll
    for (int i = 0; i < 2; i++) {
        int d1a = wm + i * 16 + r;
#pragma unroll
        for (int j = 0; j < 2; j++) {
            int d2 = wn + j * 8 + c2;
            Gp[d1a * HDIM + d2]           = acc[i][j][0];
            Gp[d1a * HDIM + d2 + 1]       = acc[i][j][1];
            Gp[(d1a + 8) * HDIM + d2]     = acc[i][j][2];
            Gp[(d1a + 8) * HDIM + d2 + 1] = acc[i][j][3];
        }
    }
}

__global__ void gram_reduce(const float* __restrict__ Gpart,
                            float* __restrict__ G, float scale)
{
    int idx = blockIdx.x * blockDim.x + threadIdx.x;
    if (idx >= 32 * HDIM * HDIM) return;
    float s = 0.f;
#pragma unroll
    for (int c = 0; c < GCHUNKS; c++)
        s += Gpart[(size_t)c * 32 * HDIM * HDIM + idx];
    G[idx] = s * scale;
}

// ---------- fused B2 build: fp16, pre-scaled ----------
__global__ __launch_bounds__(256) void w2_build(
    const float* __restrict__ Wo, const float* __restrict__ G,
    __half* __restrict__ B2h)
{
    int c0 = blockIdx.x * 64;
    int h  = blockIdx.y;
    int b  = blockIdx.z;
    const float* Gh = G + (size_t)(b * NHEADS + h) * HDIM * HDIM;

    __shared__ float Gs[64][65];
    __shared__ float Ws[64][65];
    int tid = threadIdx.x;

#pragma unroll
    for (int v = 0; v < 4; v++) {
        int idx = tid + v * 256;
        int rr = idx >> 4;
        int c = (idx & 15) << 2;
        float4 g4 = *(const float4*)(Gh + rr * HDIM + c);
        Gs[rr][c + 0] = g4.x; Gs[rr][c + 1] = g4.y;
        Gs[rr][c + 2] = g4.z; Gs[rr][c + 3] = g4.w;
        float4 w4 = make_float4(0.f, 0.f, 0.f, 0.f);
        if (c0 + rr < NCLS)
            w4 = *(const float4*)(Wo + (size_t)(c0 + rr) * EMBED + h * HDIM + c);
        Ws[rr][c + 0] = w4.x; Ws[rr][c + 1] = w4.y;
        Ws[rr][c + 2] = w4.z; Ws[rr][c + 3] = w4.w;
    }
    __syncthreads();

    int j  = tid & 63;
    int i0 = (tid >> 6) << 4;
    float acc[16];
#pragma unroll
    for (int ii = 0; ii < 16; ii++) acc[ii] = 0.f;

#pragma unroll 4
    for (int k = 0; k < 64; k++) {
        float g = Gs[k][j];
#pragma unroll
        for (int ii = 0; ii < 16; ii++)
            acc[ii] += Ws[i0 + ii][k] * g;
    }

#pragma unroll
    for (int ii = 0; ii < 16; ii++) {
        size_t o = (size_t)b * 1024 * EMBED + (size_t)(c0 + i0 + ii) * EMBED + h * HDIM + j;
        B2h[o] = __float2half_rn(acc[ii] * B2SCALE);
    }
}

// ---------- launch ----------
extern "C" void kernel_launch(void* const* d_in, const int* in_sizes, int n_in,
                              void* d_out, int out_size)
{
    const float* x     = (const float*)d_in[0];
    const float* W_in  = (const float*)d_in[1];
    const float* b_in  = (const float*)d_in[2];
    const float* W_out = (const float*)d_in[3];
    const float* b_out = (const float*)d_in[4];
    float* out = (float*)d_out;

    int M = in_sizes[0] / EMBED;   // 4096

    float *G, *Gp;
    cudaGetSymbolAddress((void**)&G, g_G);
    cudaGetSymbolAddress((void**)&Gp, g_Gpart);
    __half *xh, *wh, *phh, *b2h;
    cudaGetSymbolAddress((void**)&xh, g_xh);
    cudaGetSymbolAddress((void**)&wh, g_wh);
    cudaGetSymbolAddress((void**)&phh, g_phh);
    cudaGetSymbolAddress((void**)&b2h, g_b2h);

    cudaFuncSetAttribute(gemm_fp16, cudaFuncAttributeMaxDynamicSharedMemorySize, SMEM_BYTES);

    dim3 blk(256);

    // quantize x and W_in in one launch
    int nx4 = M * EMBED / 4, nw4 = EMBED * EMBED / 4;
    cvt_both<<<(nx4 + nw4 + 255) / 256, blk>>>((const float4*)x, (uint2*)xh, nx4,
                                               (const float4*)W_in, (uint2*)wh, nw4);

    // 1) P = X @ W_in^T + b_in  (fp16 -> phh)
    gemm_fp16<<<dim3(EMBED / BN, M / BM), blk, SMEM_BYTES>>>(
        xh, wh, b_in, 1.0f / WSCALE, nullptr, phh, EMBED, 0);

    // 2) G = (1/32) * phh_h^T phh_h
    head_gram_fp16<<<dim3(32, GCHUNKS), blk>>>(phh, Gp);
    gram_reduce<<<(32 * HDIM * HDIM + 255) / 256, blk>>>(Gp, G, 1.0f / 32.0f);

    // 3) B2[b] = blockdiag(G) @ W_out^T  (fp16, x16)
    w2_build<<<dim3(1024 / 64, NHEADS, M / SEQ), blk>>>(W_out, G, b2h);

    // 4) out = P @ B2[b]^T + b_out  (fp16)
    gemm_fp16<<<dim3(1024 / BN, M / BM), blk, SMEM_BYTES>>>(
        phh, b2h, b_out, 1.0f / B2SCALE, out, nullptr, NCLS, (long)1024 * EMBED);
}

// round 17
// speedup vs baseline: 1.2344x; 1.1146x over previous
#include <cuda_runtime.h>
#include <cuda_fp16.h>

#define EMBED 1024
#define NHEADS 16
#define HDIM 64
#define SEQ 2048
#define NCLS 1000
#define GCHUNKS 8
#define MTOT 4096

#define BM 128
#define BN 128
#define BKE 32
#define NIT (EMBED / BKE)          // 32
#define PK 40                      // padded row (elems): 80B, ldmatrix conflict-free
#define TILEB (BM * PK * 2)        // 10240 B per tile
#define STAGEB (2 * TILEB)         // 20480 {A, B}
#define NSTAGE 3
#define SMEM_BYTES (NSTAGE * STAGEB)   // 61440 -> 2 CTAs/SM

#define WSCALE 32.0f               // W_in pre-scale
#define B2SCALE 16.0f              // B2 pre-scale

// ---------- scratch ----------
__device__ float g_Gpart[GCHUNKS][32][HDIM * HDIM];
__device__ __half g_G16[32 * HDIM * HDIM];    // fp16 G, scaled 1/32
__device__ __half g_xh[MTOT * EMBED];
__device__ __half g_wh[EMBED * EMBED];
__device__ __half g_woh[1024 * EMBED];        // W_out fp16, rows >=1000 zero
__device__ __half g_phh[MTOT * EMBED];        // fp16 P
__device__ __half g_b2h[2 * 1024 * EMBED];

// ---------- helpers ----------
__device__ __forceinline__ unsigned smem_u32(const void* p) {
    unsigned a;
    asm("{ .reg .u64 t; cvta.to.shared.u64 t, %1; cvt.u32.u64 %0, t; }" : "=r"(a) : "l"(p));
    return a;
}
__device__ __forceinline__ void cpa16(unsigned s, const void* g) {
    asm volatile("cp.async.cg.shared.global [%0], [%1], 16;" :: "r"(s), "l"(g) : "memory");
}
#define CP_COMMIT() asm volatile("cp.async.commit_group;" ::: "memory")
#define CP_WAIT(n)  asm volatile("cp.async.wait_group %0;" :: "n"(n) : "memory")

#define LDSM4(r0, r1, r2, r3, a) \
    asm volatile("ldmatrix.sync.aligned.m8n8.x4.shared.b16 {%0,%1,%2,%3}, [%4];" \
        : "=r"(r0), "=r"(r1), "=r"(r2), "=r"(r3) : "r"(a))

#define LDSM4T(r0, r1, r2, r3, a) \
    asm volatile("ldmatrix.sync.aligned.m8n8.x4.trans.shared.b16 {%0,%1,%2,%3}, [%4];" \
        : "=r"(r0), "=r"(r1), "=r"(r2), "=r"(r3) : "r"(a))

#define MMAH(c, a, b0v, b1v) \
    asm volatile("mma.sync.aligned.m16n8k16.row.col.f32.f16.f16.f32 " \
        "{%0,%1,%2,%3},{%4,%5,%6,%7},{%8,%9},{%0,%1,%2,%3};" \
        : "+f"((c)[0]), "+f"((c)[1]), "+f"((c)[2]), "+f"((c)[3]) \
        : "r"((a)[0]), "r"((a)[1]), "r"((a)[2]), "r"((a)[3]), "r"(b0v), "r"(b1v))

__device__ __forceinline__ unsigned h2bits(__half2 h) {
    return *reinterpret_cast<unsigned*>(&h);
}

// ---------- cvt: x, W_in*32, W_out (rows>=1000 zeroed), one launch ----------
__global__ void cvt_all(const float4* __restrict__ X, uint2* __restrict__ XH, int nx4,
                        const float4* __restrict__ W, uint2* __restrict__ WH, int nw4,
                        const float* __restrict__ Wo, uint2* __restrict__ WoH, int nwo4)
{
    int i = blockIdx.x * blockDim.x + threadIdx.x;
    if (i < nx4) {
        float4 x = X[i];
        XH[i] = make_uint2(h2bits(__floats2half2_rn(x.x, x.y)),
                           h2bits(__floats2half2_rn(x.z, x.w)));
        return;
    }
    int j = i - nx4;
    if (j < nw4) {
        float4 w = W[j];
        WH[j] = make_uint2(h2bits(__floats2half2_rn(w.x * WSCALE, w.y * WSCALE)),
                           h2bits(__floats2half2_rn(w.z * WSCALE, w.w * WSCALE)));
        return;
    }
    int k = j - nw4;
    if (k < nwo4) {
        int row = k >> 8;                    // (k*4)/1024
        if (row >= NCLS) {
            WoH[k] = make_uint2(0, 0);
        } else {
            float4 w = *(const float4*)(Wo + (size_t)k * 4);
            WoH[k] = make_uint2(h2bits(__floats2half2_rn(w.x, w.y)),
                                h2bits(__floats2half2_rn(w.z, w.w)));
        }
    }
}

// ---------- fp16 single-term GEMM, 3-stage cp.async ring (R16, unchanged) ----------
__device__ __forceinline__ void load_stage(
    unsigned sbuf, int tid, int k0,
    const __half* A, const __half* B, int m0, int n0)
{
    int row = tid >> 1;
    int hf = tid & 1;
    unsigned soff = (unsigned)(row * PK + hf * 16) * 2;
    size_t ga = (size_t)(m0 + row) * EMBED + k0 + hf * 16;
    size_t gb = (size_t)(n0 + row) * EMBED + k0 + hf * 16;
    cpa16(sbuf + soff,              A + ga);
    cpa16(sbuf + soff + 16,         A + ga + 8);
    cpa16(sbuf + TILEB + soff,      B + gb);
    cpa16(sbuf + TILEB + soff + 16, B + gb + 8);
}

__global__ __launch_bounds__(256, 2) void gemm_fp16(
    const __half* __restrict__ A, const __half* __restrict__ BBase,
    const float* __restrict__ bias, float postScale, float* __restrict__ C,
    __half* __restrict__ Ph, int N, long bStride)
{
    extern __shared__ char smc[];
    int tid = threadIdx.x;
    int m0 = blockIdx.y * BM;
    int n0 = blockIdx.x * BN;
    unsigned sbase = smem_u32(smc);

    const __half* B = BBase + (size_t)(m0 >> 11) * bStride;

    int wid = tid >> 5, lane = tid & 31;
    int wm = (wid & 1) * 64;
    int wn = (wid >> 1) * 32;

    float acc[4][4][4];
#pragma unroll
    for (int i = 0; i < 4; i++)
#pragma unroll
        for (int j = 0; j < 4; j++)
#pragma unroll
            for (int v = 0; v < 4; v++) acc[i][j][v] = 0.f;

    load_stage(sbase, tid, 0, A, B, m0, n0);
    CP_COMMIT();
    load_stage(sbase + STAGEB, tid, BKE, A, B, m0, n0);
    CP_COMMIT();

    unsigned a_lo = (unsigned)((wm + (lane & 15)) * PK + ((lane >> 4) << 3)) * 2;
    unsigned b_lo = (unsigned)((wn + (lane & 15)) * PK + ((lane >> 4) << 3)) * 2;

    for (int it = 0; it < NIT; it++) {
        CP_WAIT(1);
        __syncthreads();
        if (it + 2 < NIT) {
            load_stage(sbase + (unsigned)((it + 2) % NSTAGE) * STAGEB, tid,
                       (it + 2) * BKE, A, B, m0, n0);
        }
        CP_COMMIT();

        unsigned sbuf = sbase + (unsigned)(it % NSTAGE) * STAGEB;
#pragma unroll
        for (int kk = 0; kk < 2; kk++) {
            unsigned ah[4][4], bb[2][4];
            unsigned ao = sbuf + a_lo + (unsigned)kk * 32;
            unsigned bo = sbuf + b_lo + (unsigned)kk * 32;

#pragma unroll
            for (int i = 0; i < 4; i++)
                LDSM4(ah[i][0], ah[i][1], ah[i][2], ah[i][3],
                      ao + (unsigned)i * (16 * PK * 2));
#pragma unroll
            for (int L = 0; L < 2; L++)
                LDSM4(bb[L][0], bb[L][1], bb[L][2], bb[L][3],
                      bo + TILEB + (unsigned)L * (16 * PK * 2));
#pragma unroll
            for (int i = 0; i < 4; i++)
#pragma unroll
                for (int j = 0; j < 4; j++) {
                    int L = j >> 1, s = j & 1;
                    MMAH(acc[i][j], ah[i], bb[L][s], bb[L][s + 2]);
                }
        }
    }

    int r = lane >> 2, c2 = (lane & 3) * 2;
#pragma unroll
    for (int i = 0; i < 4; i++) {
        int m = m0 + wm + i * 16 + r;
#pragma unroll
        for (int j = 0; j < 4; j++) {
            int n = n0 + wn + j * 8 + c2;
            float bv0 = (n < N) ? bias[n] : 0.f;
            float bv1 = (n + 1 < N) ? bias[n + 1] : 0.f;
            float v00 = acc[i][j][0] * postScale + bv0;
            float v01 = acc[i][j][1] * postScale + bv1;
            float v10 = acc[i][j][2] * postScale + bv0;
            float v11 = acc[i][j][3] * postScale + bv1;
            if (C) {
                float* C0 = C + (size_t)m * N;
                float* C1 = C0 + (size_t)8 * N;
                if (n < N)     { C0[n] = v00; C1[n] = v10; }
                if (n + 1 < N) { C0[n + 1] = v01; C1[n + 1] = v11; }
            }
            if (Ph) {
                *(unsigned*)(Ph + (size_t)m * EMBED + n) =
                    h2bits(__floats2half2_rn(v00, v01));
                *(unsigned*)(Ph + (size_t)(m + 8) * EMBED + n) =
                    h2bits(__floats2half2_rn(v10, v11));
            }
        }
    }
}

// ---------- fp16 Gram: Gpart[chunk][bh] over 256 s-rows (2 tiles of 128) ----------
#define GPD 72

__global__ __launch_bounds__(256, 4) void head_gram_fp16(
    const __half* __restrict__ ph, float* __restrict__ Gpart)
{
    __shared__ __half sh[128][GPD];

    int bh = blockIdx.x;               // 0..31
    int chunk = blockIdx.y;            // 0..7
    int b = bh >> 4;
    int h = bh & 15;
    int tid = threadIdx.x;
    int wid = tid >> 5, lane = tid & 31;
    int wm = (wid & 1) * 32;
    int wn = (wid >> 1) * 16;

    unsigned shB = smem_u32(&sh[0][0]);

    int g = lane >> 3, l = lane & 7;
    unsigned aRowOff = (unsigned)(((g & 2) ? 8 : 0) + l) * (GPD * 2);
    unsigned aColOff = (unsigned)(wm + ((g & 1) ? 8 : 0)) * 2;
    unsigned bRowOff = (unsigned)(((g & 1) ? 8 : 0) + l) * (GPD * 2);
    unsigned bColOff = (unsigned)(wn + ((g >= 2) ? 8 : 0)) * 2;

    float acc[2][2][4];
#pragma unroll
    for (int i = 0; i < 2; i++)
#pragma unroll
        for (int j = 0; j < 2; j++)
#pragma unroll
            for (int v = 0; v < 4; v++) acc[i][j][v] = 0.f;

    int row = tid >> 1;
    int q = tid & 1;
    unsigned soff = (unsigned)(row * GPD + q * 32) * 2;

    for (int half = 0; half < 2; half++) {
        size_t gbase = (size_t)(b * SEQ + chunk * 256 + half * 128 + row) * EMBED
                       + h * HDIM + q * 32;
#pragma unroll
        for (int t = 0; t < 4; t++)
            cpa16(shB + soff + t * 16, ph + gbase + t * 8);
        CP_COMMIT();
        CP_WAIT(0);
        __syncthreads();

#pragma unroll
        for (int k0 = 0; k0 < 128; k0 += 16) {
            unsigned kb = (unsigned)k0 * (GPD * 2);
            unsigned A2[2][4], B4[4];
#pragma unroll
            for (int i = 0; i < 2; i++)
                LDSM4T(A2[i][0], A2[i][1], A2[i][2], A2[i][3],
                       shB + kb + aRowOff + aColOff + (unsigned)i * 32);
            LDSM4T(B4[0], B4[1], B4[2], B4[3], shB + kb + bRowOff + bColOff);

#pragma unroll
            for (int i = 0; i < 2; i++)
#pragma unroll
                for (int j = 0; j < 2; j++)
                    MMAH(acc[i][j], A2[i], B4[j * 2], B4[j * 2 + 1]);
        }
        __syncthreads();   // all reads done before next half overwrites
    }

    float* Gp = Gpart + ((size_t)chunk * 32 + bh) * (HDIM * HDIM);
    int r = lane >> 2, c2 = (lane & 3) * 2;
#pragma unroll
    for (int i = 0; i < 2; i++) {
        int d1a = wm + i * 16 + r;
#pragma unroll
        for (int j = 0; j < 2; j++) {
            int d2 = wn + j * 8 + c2;
            Gp[d1a * HDIM + d2]           = acc[i][j][0];
            Gp[d1a * HDIM + d2 + 1]       = acc[i][j][1];
            Gp[(d1a + 8) * HDIM + d2]     = acc[i][j][2];
            Gp[(d1a + 8) * HDIM + d2 + 1] = acc[i][j][3];
        }
    }
}

// ---------- reduce -> fp16 G (scaled) ----------
__global__ void gram_reduce16(const float2* __restrict__ Gpart2,
                              __half2* __restrict__ G16, float scale)
{
    int idx = blockIdx.x * blockDim.x + threadIdx.x;   // over 32*2048
    if (idx >= 32 * HDIM * HDIM / 2) return;
    float sx = 0.f, sy = 0.f;
#pragma unroll
    for (int c = 0; c < GCHUNKS; c++) {
        float2 v = Gpart2[(size_t)c * (32 * HDIM * HDIM / 2) + idx];
        sx += v.x; sy += v.y;
    }
    G16[idx] = __floats2half2_rn(sx * scale, sy * scale);
}

// ---------- tensor-core w2: B2[b][c][h*64+j] = B2SCALE * Wo_h @ G_bh ----------
// Wo fp16 K-major (1024x1024, rows>=1000 zero); G16 symmetric 64x64 per (b,h).
__global__ __launch_bounds__(256) void w2_mma(
    const __half* __restrict__ WoH, const __half* __restrict__ G16,
    __half* __restrict__ B2h)
{
    __shared__ __half sA[128][GPD];
    __shared__ __half sB[64][GPD];

    int c0 = blockIdx.x * 128;
    int h  = blockIdx.y;
    int b  = blockIdx.z;
    int tid = threadIdx.x;
    int wid = tid >> 5, lane = tid & 31;
    int wm = (wid & 3) * 32;     // 4 m-slots
    int wn = (wid >> 2) * 32;    // 2 n-slots

    unsigned sAB = smem_u32(&sA[0][0]);
    unsigned sBB = smem_u32(&sB[0][0]);

    // load A: 128 rows x 64 k
    {
        int row = tid >> 1, hf = tid & 1;
        unsigned so = (unsigned)(row * GPD + hf * 32) * 2;
        const __half* gA = WoH + (size_t)(c0 + row) * EMBED + h * HDIM + hf * 32;
#pragma unroll
        for (int t = 0; t < 4; t++)
            cpa16(sAB + so + t * 16, gA + t * 8);
    }
    // load B: 64 rows (j) x 64 k  = G16[b,h]
    {
        int row = tid >> 2, q = tid & 3;
        unsigned so = (unsigned)(row * GPD + q * 16) * 2;
        const __half* gB = G16 + (size_t)(b * NHEADS + h) * (HDIM * HDIM) + row * HDIM + q * 16;
        cpa16(sBB + so, gB);
        cpa16(sBB + so + 16, gB + 8);
    }
    CP_COMMIT();
    CP_WAIT(0);
    __syncthreads();

    float acc[2][4][4];
#pragma unroll
    for (int i = 0; i < 2; i++)
#pragma unroll
        for (int j = 0; j < 4; j++)
#pragma unroll
            for (int v = 0; v < 4; v++) acc[i][j][v] = 0.f;

    unsigned a_lo = (unsigned)((wm + (lane & 15)) * GPD + ((lane >> 4) << 3)) * 2;
    unsigned b_lo = (unsigned)((wn + (lane & 15)) * GPD + ((lane >> 4) << 3)) * 2;

#pragma unroll
    for (int kk = 0; kk < 4; kk++) {
        unsigned ah[2][4], bb[2][4];
        unsigned ao = sAB + a_lo + (unsigned)kk * 32;
        unsigned bo = sBB + b_lo + (unsigned)kk * 32;
#pragma unroll
        for (int i = 0; i < 2; i++)
            LDSM4(ah[i][0], ah[i][1], ah[i][2], ah[i][3],
                  ao + (unsigned)i * (16 * GPD * 2));
#pragma unroll
        for (int L = 0; L < 2; L++)
            LDSM4(bb[L][0], bb[L][1], bb[L][2], bb[L][3],
                  bo + (unsigned)L * (16 * GPD * 2));
#pragma unroll
        for (int i = 0; i < 2; i++)
#pragma unroll
            for (int j = 0; j < 4; j++) {
                int L = j >> 1, s = j & 1;
                MMAH(acc[i][j], ah[i], bb[L][s], bb[L][s + 2]);
            }
    }

    int r = lane >> 2, c2 = (lane & 3) * 2;
#pragma unroll
    for (int i = 0; i < 2; i++) {
        int c = c0 + wm + i * 16 + r;
        __half* O0 = B2h + (size_t)b * 1024 * EMBED + (size_t)c * EMBED + h * HDIM;
        __half* O1 = O0 + (size_t)8 * EMBED;
#pragma unroll
        for (int j = 0; j < 4; j++) {
            int n = wn + j * 8 + c2;
            *(unsigned*)(O0 + n) = h2bits(__floats2half2_rn(acc[i][j][0] * B2SCALE,
                                                            acc[i][j][1] * B2SCALE));
            *(unsigned*)(O1 + n) = h2bits(__floats2half2_rn(acc[i][j][2] * B2SCALE,
                                                            acc[i][j][3] * B2SCALE));
        }
    }
}

// ---------- launch ----------
extern "C" void kernel_launch(void* const* d_in, const int* in_sizes, int n_in,
                              void* d_out, int out_size)
{
    const float* x     = (const float*)d_in[0];
    const float* W_in  = (const float*)d_in[1];
    const float* b_in  = (const float*)d_in[2];
    const float* W_out = (const float*)d_in[3];
    const float* b_out = (const float*)d_in[4];
    float* out = (float*)d_out;

    int M = in_sizes[0] / EMBED;   // 4096

    float* Gp;
    cudaGetSymbolAddress((void**)&Gp, g_Gpart);
    __half *xh, *wh, *woh, *phh, *b2h, *G16;
    cudaGetSymbolAddress((void**)&xh, g_xh);
    cudaGetSymbolAddress((void**)&wh, g_wh);
    cudaGetSymbolAddress((void**)&woh, g_woh);
    cudaGetSymbolAddress((void**)&phh, g_phh);
    cudaGetSymbolAddress((void**)&b2h, g_b2h);
    cudaGetSymbolAddress((void**)&G16, g_G16);

    cudaFuncSetAttribute(gemm_fp16, cudaFuncAttributeMaxDynamicSharedMemorySize, SMEM_BYTES);

    dim3 blk(256);

    // one-shot conversion: x, W_in*32, W_out(zero-padded)
    int nx4 = M * EMBED / 4, nw4 = EMBED * EMBED / 4, nwo4 = 1024 * EMBED / 4;
    cvt_all<<<(nx4 + nw4 + nwo4 + 255) / 256, blk>>>(
        (const float4*)x, (uint2*)xh, nx4,
        (const float4*)W_in, (uint2*)wh, nw4,
        W_out, (uint2*)woh, nwo4);

    // 1) P = X @ W_in^T + b_in
    gemm_fp16<<<dim3(EMBED / BN, M / BM), blk, SMEM_BYTES>>>(
        xh, wh, b_in, 1.0f / WSCALE, nullptr, phh, EMBED, 0);

    // 2) G = (1/32) * P_h^T P_h  -> fp16
    head_gram_fp16<<<dim3(32, GCHUNKS), blk>>>(phh, Gp);
    gram_reduce16<<<(32 * HDIM * HDIM / 2 + 255) / 256, blk>>>(
        (const float2*)Gp, (__half2*)G16, 1.0f / 32.0f);

    // 3) B2[b] = blockdiag(G) @ W_out^T  (tensor cores)
    w2_mma<<<dim3(1024 / 128, NHEADS, M / SEQ), blk>>>(woh, G16, b2h);

    // 4) out = P @ B2[b]^T + b_out
    gemm_fp16<<<dim3(1024 / BN, M / BM), blk, SMEM_BYTES>>>(
        phh, b2h, b_out, 1.0f / B2SCALE, out, nullptr, NCLS, (long)1024 * EMBED);
}